// round 11
// baseline (speedup 1.0000x reference)
#include <cuda_runtime.h>

#define NN   80          // row length N
#define G    4           // threads per row
#define C    20          // recursion steps per thread (G*C == NN)
#define TPB  256
#define RPC  (TPB / G)   // rows per CTA = 64
#define RWPW 8           // rows per warp
#define WBUF 1312        // per-warp smem floats (out view: 8 rows * 164)
#define SIN4 20          // in view: float4 per row
#define SOUT4 41         // out view: float4 row stride (164 floats)
#define SOUT2 82         // out view: float2 row stride

// One transfer-matrix step: new_top = (a - i)*x - b*y ; new_bottom = x.
__device__ __forceinline__ void mstep(float a, float b,
                                      float& xr, float& xi, float& yr, float& yi)
{
    float nr = a * xr + xi - b * yr;
    float ni = a * xi - xr - b * yi;
    yr = xr; yi = xi;
    xr = nr; xi = ni;
}

// 2x2 complex matmul C = A*B. Layout: {00r,00i,01r,01i,10r,10i,11r,11i}
__device__ __forceinline__ void mmul(const float* A, const float* B, float* Cm)
{
    Cm[0] = A[0]*B[0] - A[1]*B[1] + A[2]*B[4] - A[3]*B[5];
    Cm[1] = A[0]*B[1] + A[1]*B[0] + A[2]*B[5] + A[3]*B[4];
    Cm[2] = A[0]*B[2] - A[1]*B[3] + A[2]*B[6] - A[3]*B[7];
    Cm[3] = A[0]*B[3] + A[1]*B[2] + A[2]*B[7] + A[3]*B[6];
    Cm[4] = A[4]*B[0] - A[5]*B[1] + A[6]*B[4] - A[7]*B[5];
    Cm[5] = A[4]*B[1] + A[5]*B[0] + A[6]*B[5] + A[7]*B[4];
    Cm[6] = A[4]*B[2] - A[5]*B[3] + A[6]*B[6] - A[7]*B[7];
    Cm[7] = A[4]*B[3] + A[5]*B[2] + A[6]*B[7] + A[7]*B[6];
}

__global__ __launch_bounds__(TPB, 4)
void bk_green_scan11_kernel(const float* __restrict__ he,
                            const float* __restrict__ h0d,
                            const float* __restrict__ h0s,
                            const float* __restrict__ h0p,
                            float* __restrict__ out,
                            int Brows)
{
    extern __shared__ float sm[];                 // 8 warps * WBUF floats
    __shared__ float bthS[NN];   // theta beta: bc[k-1], bthS[0]=0
    __shared__ float bcS[NN];    // bc[m], bcS[NN-1]=0

    const int tid  = threadIdx.x;
    const int lane = tid & 31;
    const int wid  = tid >> 5;
    const int l    = lane & (G - 1);
    const int lrow = lane >> 2;                   // local row within warp
    const unsigned mask = 0xffffffffu;

    float* sW = sm + wid * WBUF;
    const int warpRow0 = blockIdx.x * RPC + wid * RWPW;

    if (tid < NN) {
        bcS[tid]  = (tid <= NN - 2) ? h0s[tid] * h0p[tid] : 0.0f;
        bthS[tid] = (tid == 0) ? 0.0f : h0s[tid - 1] * h0p[tid - 1];
    }
    __syncthreads();

    // ---- warp-local coalesced in-staging: sW[row][j] = he + h0d ----
    {
        const float4* h4 = (const float4*)he;
        const float4* d4 = (const float4*)h0d;
        float4* sW4 = (float4*)sW;
        size_t gmax = (size_t)Brows * SIN4 - 1;
        size_t gbase = (size_t)warpRow0 * SIN4;
        #pragma unroll
        for (int k = 0; k < 5; k++) {
            int idx = lane + 32 * k;              // 0..159
            int c = idx % SIN4;
            size_t gidx = gbase + idx;
            if (gidx > gmax) gidx = gmax;
            float4 hv = __ldg(h4 + gidx);
            float4 dv = __ldg(d4 + c);
            float4 v; v.x = hv.x + dv.x; v.y = hv.y + dv.y;
            v.z = hv.z + dv.z; v.w = hv.w + dv.w;
            sW4[idx] = v;
        }
    }
    __syncwarp();

    const int j0 = C * l;

    // ---- read own a-chunk (LDS.128, stride 20 f4: conflict-free) ----
    float a_reg[C];
    {
        const float4* s4 = (const float4*)sW + lrow * SIN4 + l * 5;
        #pragma unroll
        for (int q = 0; q < C / 4; q++) {
            float4 v = s4[q];
            a_reg[4*q+0] = v.x; a_reg[4*q+1] = v.y;
            a_reg[4*q+2] = v.z; a_reg[4*q+3] = v.w;
        }
    }
    __syncwarp();   // in-buffer dead; reused for phi/out staging below

    // ---- build THETA chunk matrix (2 columns) ----
    float Jp[8] = {1.f,0.f, 0.f,0.f, 0.f,0.f, 1.f,0.f};
    #pragma unroll
    for (int r = 0; r < C; r++) {
        float at = a_reg[r], bt = bthS[j0 + r];
        mstep(at, bt, Jp[0], Jp[1], Jp[4], Jp[5]);   // col 0
        mstep(at, bt, Jp[2], Jp[3], Jp[6], Jp[7]);   // col 1
    }
    float Js[8];
    #pragma unroll
    for (int i = 0; i < 8; i++) Js[i] = Jp[i];

    // ---- round d=1: full combines, both scans ----
    {
        float Tu[8], Td[8], Ru[8], Rd[8];
        #pragma unroll
        for (int i = 0; i < 8; i++) Tu[i] = __shfl_up_sync(mask, Jp[i], 1, G);
        #pragma unroll
        for (int i = 0; i < 8; i++) Td[i] = __shfl_down_sync(mask, Js[i], 1, G);
        mmul(Jp, Tu, Ru);           // own * received
        mmul(Td, Js, Rd);           // received * own
        bool useu = (l >= 1);
        bool used = (l <= G - 2);
        #pragma unroll
        for (int i = 0; i < 8; i++) {
            Jp[i] = useu ? Ru[i] : Jp[i];
            Js[i] = used ? Rd[i] : Js[i];
        }
    }

    // ---- round d=2 (final): partial combines ----
    {
        // ascending: only first column of result needed (prefix + denominator).
        float Tu0 = __shfl_up_sync(mask, Jp[0], 2, G);
        float Tu1 = __shfl_up_sync(mask, Jp[1], 2, G);
        float Tu4 = __shfl_up_sync(mask, Jp[4], 2, G);
        float Tu5 = __shfl_up_sync(mask, Jp[5], 2, G);
        float Ru0 = Jp[0]*Tu0 - Jp[1]*Tu1 + Jp[2]*Tu4 - Jp[3]*Tu5;
        float Ru1 = Jp[0]*Tu1 + Jp[1]*Tu0 + Jp[2]*Tu5 + Jp[3]*Tu4;
        float Ru4 = Jp[4]*Tu0 - Jp[5]*Tu1 + Jp[6]*Tu4 - Jp[7]*Tu5;
        float Ru5 = Jp[4]*Tu1 + Jp[5]*Tu0 + Jp[6]*Tu5 + Jp[7]*Tu4;
        bool useu = (l >= 2);
        Jp[0] = useu ? Ru0 : Jp[0];
        Jp[1] = useu ? Ru1 : Jp[1];
        Jp[4] = useu ? Ru4 : Jp[4];
        Jp[5] = useu ? Ru5 : Jp[5];

        // descending: only row 0 of result needed (phi boundary).
        float Td0 = __shfl_down_sync(mask, Js[0], 2, G);
        float Td1 = __shfl_down_sync(mask, Js[1], 2, G);
        float Td2 = __shfl_down_sync(mask, Js[2], 2, G);
        float Td3 = __shfl_down_sync(mask, Js[3], 2, G);
        float Rd0 = Td0*Js[0] - Td1*Js[1] + Td2*Js[4] - Td3*Js[5];
        float Rd1 = Td0*Js[1] + Td1*Js[0] + Td2*Js[5] + Td3*Js[4];
        float Rd2 = Td0*Js[2] - Td1*Js[3] + Td2*Js[6] - Td3*Js[7];
        float Rd3 = Td0*Js[3] + Td1*Js[2] + Td2*Js[7] + Td3*Js[6];
        bool used = (l <= G - 3);
        Js[0] = used ? Rd0 : Js[0];
        Js[1] = used ? Rd1 : Js[1];
        Js[2] = used ? Rd2 : Js[2];
        Js[3] = used ? Rd3 : Js[3];
    }

    // denominator: theta_N = [Jp(lane G-1)]_00 ; e = conj(theta_N)/|theta_N|^2
    float exr, exi;
    {
        float dr = __shfl_sync(mask, Jp[0], G - 1, G);
        float di = __shfl_sync(mask, Jp[1], G - 1, G);
        float inv = 1.0f / (dr * dr + di * di);
        exr = dr * inv; exi = -di * inv;
    }

    // theta exclusive prefix state, scaled by e (linearity: theta' = e*theta)
    float sxr, sxi, syr, syi;
    {
        float q0 = __shfl_up_sync(mask, Jp[0], 1, G);
        float q1 = __shfl_up_sync(mask, Jp[1], 1, G);
        float q4 = __shfl_up_sync(mask, Jp[4], 1, G);
        float q5 = __shfl_up_sync(mask, Jp[5], 1, G);
        float xr = (l == 0) ? 1.f : q0;
        float xi = (l == 0) ? 0.f : q1;
        float yr = (l == 0) ? 0.f : q4;
        float yi = (l == 0) ? 0.f : q5;
        sxr = xr * exr - xi * exi;  sxi = xr * exi + xi * exr;
        syr = yr * exr - yi * exi;  syi = yr * exi + yi * exr;
    }

    // phi boundary from exclusive suffix T(p), p=j0+C:
    //   top = T[0][0]; bottom = -T[0][1] / bc_{p-1}
    float pxr, pxi, qyr, qyi;
    {
        float q0 = __shfl_down_sync(mask, Js[0], 1, G);
        float q1 = __shfl_down_sync(mask, Js[1], 1, G);
        float q2 = __shfl_down_sync(mask, Js[2], 1, G);
        float q3 = __shfl_down_sync(mask, Js[3], 1, G);
        float nbinv = -1.0f / bcS[j0 + C - 1];   // garbage for l==G-1, selected away
        pxr = (l == G - 1) ? 1.f : q0;
        pxi = (l == G - 1) ? 0.f : q1;
        qyr = (l == G - 1) ? 0.f : (q2 * nbinv);
        qyi = (l == G - 1) ? 0.f : (q3 * nbinv);
    }

    // thread's float2 window in the out view: elements j0..j0+19 of local row
    float2* so2 = (float2*)sW + lrow * SOUT2 + j0;

    // ---- phi replay: store phi_rev pair r' at element slot (C-1-r') ----
    // (slot r then holds phi needed by theta step r; thread-private, no sync)
    #pragma unroll
    for (int r = 0; r < C; r++) {
        float2 ph; ph.x = pxr; ph.y = pxi;
        so2[C - 1 - r] = ph;
        float ap = a_reg[C-1-r], bp = bcS[j0 + C - 1 - r];
        mstep(ap, bp, pxr, pxi, qyr, qyi);
    }

    // ---- theta' replay: read phi slot r, overwrite with g_r in place ----
    #pragma unroll
    for (int r = 0; r < C; r++) {
        float2 q = so2[r];
        float2 g;
        g.x = sxr * q.x - sxi * q.y;
        g.y = sxr * q.y + sxi * q.x;
        so2[r] = g;
        float at = a_reg[r], bt = bthS[j0 + r];
        mstep(at, bt, sxr, sxi, syr, syi);
    }
    __syncwarp();

    // ---- coalesced out: smem (stride 41 f4) -> global float4 ----
    {
        const float4* so4 = (const float4*)sW;
        float4* out4 = (float4*)out + (size_t)warpRow0 * (NN / 2);
        #pragma unroll
        for (int k = 0; k < 10; k++) {
            int idx = lane + 32 * k;              // 0..319
            int r = idx / (NN / 2);
            int c = idx - r * (NN / 2);
            if (warpRow0 + r < Brows)
                out4[idx] = so4[r * SOUT4 + c];
        }
    }
}

extern "C" void kernel_launch(void* const* d_in, const int* in_sizes, int n_in,
                              void* d_out, int out_size)
{
    const float* he  = (const float*)d_in[0];   // he_diag (B*N)
    const float* h0d = (const float*)d_in[1];   // h0_diag (N)
    const float* h0s = (const float*)d_in[2];   // h0_sub  (N-1)
    const float* h0p = (const float*)d_in[3];   // h0_super(N-1)

    int Brows = in_sizes[0] / NN;
    size_t smem = (size_t)(TPB / 32) * WBUF * sizeof(float);   // 41,984 B

    cudaFuncSetAttribute(bk_green_scan11_kernel,
                         cudaFuncAttributeMaxDynamicSharedMemorySize, (int)smem);

    int grid = (Brows + RPC - 1) / RPC;
    bk_green_scan11_kernel<<<grid, TPB, smem>>>(he, h0d, h0s, h0p, (float*)d_out, Brows);
}

// round 13
// speedup vs baseline: 1.0656x; 1.0656x over previous
#include <cuda_runtime.h>

#define NN   80          // row length N
#define G    4           // threads per row
#define C    20          // recursion steps per thread (G*C == NN)
#define H    10          // half chunk
#define TPB  256
#define RPC  (TPB / G)   // rows per CTA = 64
#define RWPW 8           // rows per warp
#define WBUF 1312        // per-warp smem floats (out view: 8 rows * 164)
#define SIN4 20          // in view: float4 per row
#define SOUT4 41         // out view: float4 row stride

// One transfer-matrix step: new_top = (a - i)*x - b*y ; new_bottom = x.
__device__ __forceinline__ void mstep(float a, float b,
                                      float& xr, float& xi, float& yr, float& yi)
{
    float nr = a * xr + xi - b * yr;
    float ni = a * xi - xr - b * yi;
    yr = xr; yi = xi;
    xr = nr; xi = ni;
}

// 2x2 complex matmul C = A*B. Layout: {00r,00i,01r,01i,10r,10i,11r,11i}
__device__ __forceinline__ void mmul(const float* A, const float* B, float* Cm)
{
    Cm[0] = A[0]*B[0] - A[1]*B[1] + A[2]*B[4] - A[3]*B[5];
    Cm[1] = A[0]*B[1] + A[1]*B[0] + A[2]*B[5] + A[3]*B[4];
    Cm[2] = A[0]*B[2] - A[1]*B[3] + A[2]*B[6] - A[3]*B[7];
    Cm[3] = A[0]*B[3] + A[1]*B[2] + A[2]*B[7] + A[3]*B[6];
    Cm[4] = A[4]*B[0] - A[5]*B[1] + A[6]*B[4] - A[7]*B[5];
    Cm[5] = A[4]*B[1] + A[5]*B[0] + A[6]*B[5] + A[7]*B[4];
    Cm[6] = A[4]*B[2] - A[5]*B[3] + A[6]*B[6] - A[7]*B[7];
    Cm[7] = A[4]*B[3] + A[5]*B[2] + A[6]*B[7] + A[7]*B[6];
}

__global__ __launch_bounds__(TPB, 4)
void bk_green_scan13_kernel(const float* __restrict__ he,
                            const float* __restrict__ h0d,
                            const float* __restrict__ h0s,
                            const float* __restrict__ h0p,
                            float* __restrict__ out,
                            int Brows)
{
    extern __shared__ float sm[];                 // 8 warps * WBUF floats
    __shared__ float bthS[NN];   // theta beta: bc[k-1], bthS[0]=0
    __shared__ float bcS[NN];    // bc[m], bcS[NN-1]=0

    const int tid  = threadIdx.x;
    const int lane = tid & 31;
    const int wid  = tid >> 5;
    const int l    = lane & (G - 1);
    const int lrow = lane >> 2;                   // local row within warp
    const unsigned mask = 0xffffffffu;

    float* sW = sm + wid * WBUF;
    const int warpRow0 = blockIdx.x * RPC + wid * RWPW;

    if (tid < NN) {
        bcS[tid]  = (tid <= NN - 2) ? h0s[tid] * h0p[tid] : 0.0f;
        bthS[tid] = (tid == 0) ? 0.0f : h0s[tid - 1] * h0p[tid - 1];
    }
    __syncthreads();

    // ---- warp-local coalesced in-staging: sW[row][j] = he + h0d ----
    {
        const float4* h4 = (const float4*)he;
        const float4* d4 = (const float4*)h0d;
        float4* sW4 = (float4*)sW;
        size_t gmax = (size_t)Brows * SIN4 - 1;
        size_t gbase = (size_t)warpRow0 * SIN4;
        #pragma unroll
        for (int k = 0; k < 5; k++) {
            int idx = lane + 32 * k;              // 0..159
            int c = idx % SIN4;
            size_t gidx = gbase + idx;
            if (gidx > gmax) gidx = gmax;
            float4 hv = __ldg(h4 + gidx);
            float4 dv = __ldg(d4 + c);
            float4 v; v.x = hv.x + dv.x; v.y = hv.y + dv.y;
            v.z = hv.z + dv.z; v.w = hv.w + dv.w;
            sW4[idx] = v;
        }
    }
    __syncwarp();

    const int j0 = C * l;

    // ---- read own a-chunk (LDS.128, stride 20 f4: conflict-free) ----
    float a_reg[C];
    {
        const float4* s4 = (const float4*)sW + lrow * SIN4 + l * 5;
        #pragma unroll
        for (int q = 0; q < C / 4; q++) {
            float4 v = s4[q];
            a_reg[4*q+0] = v.x; a_reg[4*q+1] = v.y;
            a_reg[4*q+2] = v.z; a_reg[4*q+3] = v.w;
        }
    }
    __syncwarp();   // in-buffer dead; reused for out staging

    // ---- build THETA chunk matrix (2 columns) ----
    float Jp[8] = {1.f,0.f, 0.f,0.f, 0.f,0.f, 1.f,0.f};
    #pragma unroll
    for (int r = 0; r < C; r++) {
        float at = a_reg[r], bt = bthS[j0 + r];
        mstep(at, bt, Jp[0], Jp[1], Jp[4], Jp[5]);   // col 0
        mstep(at, bt, Jp[2], Jp[3], Jp[6], Jp[7]);   // col 1
    }
    float Js[8];
    #pragma unroll
    for (int i = 0; i < 8; i++) Js[i] = Jp[i];

    // ---- round d=1: full combines, both scans ----
    {
        float Tu[8], Td[8], Ru[8], Rd[8];
        #pragma unroll
        for (int i = 0; i < 8; i++) Tu[i] = __shfl_up_sync(mask, Jp[i], 1, G);
        #pragma unroll
        for (int i = 0; i < 8; i++) Td[i] = __shfl_down_sync(mask, Js[i], 1, G);
        mmul(Jp, Tu, Ru);           // own * received
        mmul(Td, Js, Rd);           // received * own
        bool useu = (l >= 1);
        bool used = (l <= G - 2);
        #pragma unroll
        for (int i = 0; i < 8; i++) {
            Jp[i] = useu ? Ru[i] : Jp[i];
            Js[i] = used ? Rd[i] : Js[i];
        }
    }

    // ---- round d=2 (final): partial combines ----
    {
        // ascending: only first column of result needed (prefix + denominator).
        float Tu0 = __shfl_up_sync(mask, Jp[0], 2, G);
        float Tu1 = __shfl_up_sync(mask, Jp[1], 2, G);
        float Tu4 = __shfl_up_sync(mask, Jp[4], 2, G);
        float Tu5 = __shfl_up_sync(mask, Jp[5], 2, G);
        float Ru0 = Jp[0]*Tu0 - Jp[1]*Tu1 + Jp[2]*Tu4 - Jp[3]*Tu5;
        float Ru1 = Jp[0]*Tu1 + Jp[1]*Tu0 + Jp[2]*Tu5 + Jp[3]*Tu4;
        float Ru4 = Jp[4]*Tu0 - Jp[5]*Tu1 + Jp[6]*Tu4 - Jp[7]*Tu5;
        float Ru5 = Jp[4]*Tu1 + Jp[5]*Tu0 + Jp[6]*Tu5 + Jp[7]*Tu4;
        bool useu = (l >= 2);
        Jp[0] = useu ? Ru0 : Jp[0];
        Jp[1] = useu ? Ru1 : Jp[1];
        Jp[4] = useu ? Ru4 : Jp[4];
        Jp[5] = useu ? Ru5 : Jp[5];

        // descending: only row 0 of result needed (phi boundary).
        float Td0 = __shfl_down_sync(mask, Js[0], 2, G);
        float Td1 = __shfl_down_sync(mask, Js[1], 2, G);
        float Td2 = __shfl_down_sync(mask, Js[2], 2, G);
        float Td3 = __shfl_down_sync(mask, Js[3], 2, G);
        float Rd0 = Td0*Js[0] - Td1*Js[1] + Td2*Js[4] - Td3*Js[5];
        float Rd1 = Td0*Js[1] + Td1*Js[0] + Td2*Js[5] + Td3*Js[4];
        float Rd2 = Td0*Js[2] - Td1*Js[3] + Td2*Js[6] - Td3*Js[7];
        float Rd3 = Td0*Js[3] + Td1*Js[2] + Td2*Js[7] + Td3*Js[6];
        bool used = (l <= G - 3);
        Js[0] = used ? Rd0 : Js[0];
        Js[1] = used ? Rd1 : Js[1];
        Js[2] = used ? Rd2 : Js[2];
        Js[3] = used ? Rd3 : Js[3];
    }

    // denominator: theta_N = [Jp(lane G-1)]_00 ; e = conj(theta_N)/|theta_N|^2
    float exr, exi;
    {
        float dr = __shfl_sync(mask, Jp[0], G - 1, G);
        float di = __shfl_sync(mask, Jp[1], G - 1, G);
        float inv = 1.0f / (dr * dr + di * di);
        exr = dr * inv; exi = -di * inv;
    }

    // theta exclusive prefix state, scaled by e (theta' = e*theta)
    float sxr, sxi, syr, syi;
    {
        float q0 = __shfl_up_sync(mask, Jp[0], 1, G);
        float q1 = __shfl_up_sync(mask, Jp[1], 1, G);
        float q4 = __shfl_up_sync(mask, Jp[4], 1, G);
        float q5 = __shfl_up_sync(mask, Jp[5], 1, G);
        float xr = (l == 0) ? 1.f : q0;
        float xi = (l == 0) ? 0.f : q1;
        float yr = (l == 0) ? 0.f : q4;
        float yi = (l == 0) ? 0.f : q5;
        sxr = xr * exr - xi * exi;  sxi = xr * exi + xi * exr;
        syr = yr * exr - yi * exi;  syi = yr * exi + yi * exr;
    }
    // saved copy for the second theta pass (forward, stable)
    const float s0xr = sxr, s0xi = sxi, s0yr = syr, s0yi = syi;

    // phi boundary from exclusive suffix T(p), p=j0+C:
    //   top = T[0][0]; bottom = -T[0][1] / bc_{p-1}
    float pxr, pxi, qyr, qyi;
    {
        float q0 = __shfl_down_sync(mask, Js[0], 1, G);
        float q1 = __shfl_down_sync(mask, Js[1], 1, G);
        float q2 = __shfl_down_sync(mask, Js[2], 1, G);
        float q3 = __shfl_down_sync(mask, Js[3], 1, G);
        float nbinv = -1.0f / bcS[j0 + C - 1];   // garbage for l==G-1, selected away
        pxr = (l == G - 1) ? 1.f : q0;
        pxi = (l == G - 1) ? 0.f : q1;
        qyr = (l == G - 1) ? 0.f : (q2 * nbinv);
        qyi = (l == G - 1) ? 0.f : (q3 * nbinv);
    }

    float4* so4 = (float4*)sW + lrow * SOUT4 + l * (C / 2);
    float phr[H], phi_[H];

    // ---- Phase 1: phi replay steps 0..H-1, buffer phi_{m0..m0+H-1} ----
    #pragma unroll
    for (int r = 0; r < H; r++) {
        phr[r] = pxr; phi_[r] = pxi;
        float ap = a_reg[C-1-r], bp = bcS[j0 + C - 1 - r];
        mstep(ap, bp, pxr, pxi, qyr, qyi);
    }

    // ---- Phase 2: theta advance r=0..H-1 silently, then emit r=H..C-1 ----
    #pragma unroll
    for (int r = 0; r < H; r++) {
        float at = a_reg[r], bt = bthS[j0 + r];
        mstep(at, bt, sxr, sxi, syr, syi);
    }
    {
        float gx = 0.f, gy = 0.f;
        #pragma unroll
        for (int r = H; r < C; r++) {
            // theta_{j0+r} pairs phi_{m0+C-1-r} = buffer slot C-1-r (in 0..H-1)
            float qr = phr[C-1-r], qi = phi_[C-1-r];
            float g0 = sxr * qr - sxi * qi;
            float g1 = sxr * qi + sxi * qr;
            if ((r & 1) == 0) { gx = g0; gy = g1; }
            else {
                float4 g; g.x = gx; g.y = gy; g.z = g0; g.w = g1;
                so4[r >> 1] = g;
            }
            float at = a_reg[r], bt = bthS[j0 + r];
            mstep(at, bt, sxr, sxi, syr, syi);
        }
    }

    // ---- Phase 3: phi replay steps H..C-1 into same buffer ----
    #pragma unroll
    for (int r = 0; r < H; r++) {
        phr[r] = pxr; phi_[r] = pxi;          // phi_{m0+H+r}
        float ap = a_reg[C-1-H-r], bp = bcS[j0 + C - 1 - H - r];
        mstep(ap, bp, pxr, pxi, qyr, qyi);
    }

    // ---- Phase 4: theta replay r=0..H-1 from saved prefix, emit ----
    {
        float txr = s0xr, txi = s0xi, tyr = s0yr, tyi = s0yi;
        float gx = 0.f, gy = 0.f;
        #pragma unroll
        for (int r = 0; r < H; r++) {
            // theta_{j0+r} pairs phi_{m0+C-1-r}; buffer slot (C-1-r)-H = H-1-r
            float qr = phr[H-1-r], qi = phi_[H-1-r];
            float g0 = txr * qr - txi * qi;
            float g1 = txr * qi + txi * qr;
            if ((r & 1) == 0) { gx = g0; gy = g1; }
            else {
                float4 g; g.x = gx; g.y = gy; g.z = g0; g.w = g1;
                so4[r >> 1] = g;
            }
            float at = a_reg[r], bt = bthS[j0 + r];
            mstep(at, bt, txr, txi, tyr, tyi);
        }
    }
    __syncwarp();

    // ---- coalesced out: smem (stride 41 f4) -> global float4 ----
    {
        const float4* sof = (const float4*)sW;
        float4* out4 = (float4*)out + (size_t)warpRow0 * (NN / 2);
        #pragma unroll
        for (int k = 0; k < 10; k++) {
            int idx = lane + 32 * k;              // 0..319
            int r = idx / (NN / 2);
            int c = idx - r * (NN / 2);
            if (warpRow0 + r < Brows)
                out4[idx] = sof[r * SOUT4 + c];
        }
    }
}

extern "C" void kernel_launch(void* const* d_in, const int* in_sizes, int n_in,
                              void* d_out, int out_size)
{
    const float* he  = (const float*)d_in[0];   // he_diag (B*N)
    const float* h0d = (const float*)d_in[1];   // h0_diag (N)
    const float* h0s = (const float*)d_in[2];   // h0_sub  (N-1)
    const float* h0p = (const float*)d_in[3];   // h0_super(N-1)

    int Brows = in_sizes[0] / NN;
    size_t smem = (size_t)(TPB / 32) * WBUF * sizeof(float);   // 41,984 B

    cudaFuncSetAttribute(bk_green_scan13_kernel,
                         cudaFuncAttributeMaxDynamicSharedMemorySize, (int)smem);

    int grid = (Brows + RPC - 1) / RPC;
    bk_green_scan13_kernel<<<grid, TPB, smem>>>(he, h0d, h0s, h0p, (float*)d_out, Brows);
}

// round 14
// speedup vs baseline: 1.1405x; 1.0703x over previous
#include <cuda_runtime.h>

#define NN   80          // row length N
#define G    4           // threads per row
#define C    20          // recursion steps per thread (G*C == NN)
#define TPB  256
#define RPC  (TPB / G)   // rows per CTA = 64
#define RWPW 8           // rows per warp
#define WBUF 1312        // per-warp smem floats (out view: 8 rows * 164)
#define SIN4 20          // in view: float4 per row
#define SOUT4 41         // out view: float4 row stride

// One transfer-matrix step: new_top = (a - i)*x - b*y ; new_bottom = x.
__device__ __forceinline__ void mstep(float a, float b,
                                      float& xr, float& xi, float& yr, float& yi)
{
    float nr = a * xr + xi - b * yr;
    float ni = a * xi - xr - b * yi;
    yr = xr; yi = xi;
    xr = nr; xi = ni;
}

// 2x2 complex matmul C = A*B. Layout: {00r,00i,01r,01i,10r,10i,11r,11i}
__device__ __forceinline__ void mmul(const float* A, const float* B, float* Cm)
{
    Cm[0] = A[0]*B[0] - A[1]*B[1] + A[2]*B[4] - A[3]*B[5];
    Cm[1] = A[0]*B[1] + A[1]*B[0] + A[2]*B[5] + A[3]*B[4];
    Cm[2] = A[0]*B[2] - A[1]*B[3] + A[2]*B[6] - A[3]*B[7];
    Cm[3] = A[0]*B[3] + A[1]*B[2] + A[2]*B[7] + A[3]*B[6];
    Cm[4] = A[4]*B[0] - A[5]*B[1] + A[6]*B[4] - A[7]*B[5];
    Cm[5] = A[4]*B[1] + A[5]*B[0] + A[6]*B[5] + A[7]*B[4];
    Cm[6] = A[4]*B[2] - A[5]*B[3] + A[6]*B[6] - A[7]*B[7];
    Cm[7] = A[4]*B[3] + A[5]*B[2] + A[6]*B[7] + A[7]*B[6];
}

// Core per-thread computation after input staging.
// UB = true  -> all bc values are exactly 1.0f (verified by caller); b's become
//              compile-time 1.0f except the two structural zeros (bth[0], bc[NN-1]).
// UB = false -> general path: b's read from shared arrays (R10 behavior).
template<bool UB>
__device__ __forceinline__ void bk_core(float* sW, const float* bthS, const float* bcS,
                                        int l, int lrow, unsigned mask)
{
    const int j0 = C * l;

    // ---- read own a-chunk (LDS.128, stride 20 f4: conflict-free) ----
    float a_reg[C];
    {
        const float4* s4 = (const float4*)sW + lrow * SIN4 + l * 5;
        #pragma unroll
        for (int q = 0; q < C / 4; q++) {
            float4 v = s4[q];
            a_reg[4*q+0] = v.x; a_reg[4*q+1] = v.y;
            a_reg[4*q+2] = v.z; a_reg[4*q+3] = v.w;
        }
    }
    __syncwarp();   // in-buffer dead; reused for out staging

    // ---- build THETA chunk matrix (2 columns) ----
    float Jp[8] = {1.f,0.f, 0.f,0.f, 0.f,0.f, 1.f,0.f};
    #pragma unroll
    for (int r = 0; r < C; r++) {
        float at = a_reg[r];
        float bt = UB ? ((r == 0 && l == 0) ? 0.f : 1.f) : bthS[j0 + r];
        mstep(at, bt, Jp[0], Jp[1], Jp[4], Jp[5]);   // col 0
        mstep(at, bt, Jp[2], Jp[3], Jp[6], Jp[7]);   // col 1
    }
    float Js[8];
    #pragma unroll
    for (int i = 0; i < 8; i++) Js[i] = Jp[i];

    // ---- round d=1: full combines, both scans ----
    {
        float Tu[8], Td[8], Ru[8], Rd[8];
        #pragma unroll
        for (int i = 0; i < 8; i++) Tu[i] = __shfl_up_sync(mask, Jp[i], 1, G);
        #pragma unroll
        for (int i = 0; i < 8; i++) Td[i] = __shfl_down_sync(mask, Js[i], 1, G);
        mmul(Jp, Tu, Ru);           // own * received
        mmul(Td, Js, Rd);           // received * own
        bool useu = (l >= 1);
        bool used = (l <= G - 2);
        #pragma unroll
        for (int i = 0; i < 8; i++) {
            Jp[i] = useu ? Ru[i] : Jp[i];
            Js[i] = used ? Rd[i] : Js[i];
        }
    }

    // ---- round d=2 (final): partial combines ----
    {
        // ascending: only first column of result needed (prefix + denominator).
        float Tu0 = __shfl_up_sync(mask, Jp[0], 2, G);
        float Tu1 = __shfl_up_sync(mask, Jp[1], 2, G);
        float Tu4 = __shfl_up_sync(mask, Jp[4], 2, G);
        float Tu5 = __shfl_up_sync(mask, Jp[5], 2, G);
        float Ru0 = Jp[0]*Tu0 - Jp[1]*Tu1 + Jp[2]*Tu4 - Jp[3]*Tu5;
        float Ru1 = Jp[0]*Tu1 + Jp[1]*Tu0 + Jp[2]*Tu5 + Jp[3]*Tu4;
        float Ru4 = Jp[4]*Tu0 - Jp[5]*Tu1 + Jp[6]*Tu4 - Jp[7]*Tu5;
        float Ru5 = Jp[4]*Tu1 + Jp[5]*Tu0 + Jp[6]*Tu5 + Jp[7]*Tu4;
        bool useu = (l >= 2);
        Jp[0] = useu ? Ru0 : Jp[0];
        Jp[1] = useu ? Ru1 : Jp[1];
        Jp[4] = useu ? Ru4 : Jp[4];
        Jp[5] = useu ? Ru5 : Jp[5];

        // descending: only row 0 of result needed (phi boundary).
        float Td0 = __shfl_down_sync(mask, Js[0], 2, G);
        float Td1 = __shfl_down_sync(mask, Js[1], 2, G);
        float Td2 = __shfl_down_sync(mask, Js[2], 2, G);
        float Td3 = __shfl_down_sync(mask, Js[3], 2, G);
        float Rd0 = Td0*Js[0] - Td1*Js[1] + Td2*Js[4] - Td3*Js[5];
        float Rd1 = Td0*Js[1] + Td1*Js[0] + Td2*Js[5] + Td3*Js[4];
        float Rd2 = Td0*Js[2] - Td1*Js[3] + Td2*Js[6] - Td3*Js[7];
        float Rd3 = Td0*Js[3] + Td1*Js[2] + Td2*Js[7] + Td3*Js[6];
        bool used = (l <= G - 3);
        Js[0] = used ? Rd0 : Js[0];
        Js[1] = used ? Rd1 : Js[1];
        Js[2] = used ? Rd2 : Js[2];
        Js[3] = used ? Rd3 : Js[3];
    }

    // denominator: theta_N = [Jp(lane G-1)]_00 ; e = conj(theta_N)/|theta_N|^2
    float exr, exi;
    {
        float dr = __shfl_sync(mask, Jp[0], G - 1, G);
        float di = __shfl_sync(mask, Jp[1], G - 1, G);
        float inv = 1.0f / (dr * dr + di * di);
        exr = dr * inv; exi = -di * inv;
    }

    // theta exclusive prefix state, scaled by e (theta' = e*theta)
    float sxr, sxi, syr, syi;
    {
        float q0 = __shfl_up_sync(mask, Jp[0], 1, G);
        float q1 = __shfl_up_sync(mask, Jp[1], 1, G);
        float q4 = __shfl_up_sync(mask, Jp[4], 1, G);
        float q5 = __shfl_up_sync(mask, Jp[5], 1, G);
        float xr = (l == 0) ? 1.f : q0;
        float xi = (l == 0) ? 0.f : q1;
        float yr = (l == 0) ? 0.f : q4;
        float yi = (l == 0) ? 0.f : q5;
        sxr = xr * exr - xi * exi;  sxi = xr * exi + xi * exr;
        syr = yr * exr - yi * exi;  syi = yr * exi + yi * exr;
    }

    // phi boundary from exclusive suffix T(p), p=j0+C:
    //   top = T[0][0]; bottom = -T[0][1] / bc_{p-1}
    float pxr, pxi, qyr, qyi;
    {
        float q0 = __shfl_down_sync(mask, Js[0], 1, G);
        float q1 = __shfl_down_sync(mask, Js[1], 1, G);
        float q2 = __shfl_down_sync(mask, Js[2], 1, G);
        float q3 = __shfl_down_sync(mask, Js[3], 1, G);
        float nbinv = UB ? -1.0f : (-1.0f / bcS[j0 + C - 1]);  // l==G-1 selected away
        pxr = (l == G - 1) ? 1.f : q0;
        pxi = (l == G - 1) ? 0.f : q1;
        qyr = (l == G - 1) ? 0.f : (q2 * nbinv);
        qyi = (l == G - 1) ? 0.f : (q3 * nbinv);
    }

    // ---- phi replay into registers ----
    float phr[C], phi_[C];
    #pragma unroll
    for (int r = 0; r < C; r++) {
        phr[r] = pxr; phi_[r] = pxi;
        float ap = a_reg[C-1-r];
        float bp = UB ? ((r == 0 && l == G - 1) ? 0.f : 1.f)
                      : bcS[j0 + C - 1 - r];
        mstep(ap, bp, pxr, pxi, qyr, qyi);
    }

    // ---- theta' replay fused with g = theta' * phi, staged to smem ----
    {
        float4* so4 = (float4*)sW + lrow * SOUT4 + l * (C / 2);
        float gx = 0.f, gy = 0.f;
        #pragma unroll
        for (int r = 0; r < C; r++) {
            float qr = phr[C-1-r], qi = phi_[C-1-r];
            float g0 = sxr * qr - sxi * qi;
            float g1 = sxr * qi + sxi * qr;
            if ((r & 1) == 0) { gx = g0; gy = g1; }
            else {
                float4 g; g.x = gx; g.y = gy; g.z = g0; g.w = g1;
                so4[r >> 1] = g;
            }
            float at = a_reg[r];
            float bt = UB ? ((r == 0 && l == 0) ? 0.f : 1.f) : bthS[j0 + r];
            mstep(at, bt, sxr, sxi, syr, syi);
        }
    }
}

__global__ __launch_bounds__(TPB, 3)
void bk_green_scan14_kernel(const float* __restrict__ he,
                            const float* __restrict__ h0d,
                            const float* __restrict__ h0s,
                            const float* __restrict__ h0p,
                            float* __restrict__ out,
                            int Brows)
{
    extern __shared__ float sm[];                 // 8 warps * WBUF floats
    __shared__ float bthS[NN];   // theta beta: bc[k-1], bthS[0]=0
    __shared__ float bcS[NN];    // bc[m], bcS[NN-1]=0

    const int tid  = threadIdx.x;
    const int lane = tid & 31;
    const int wid  = tid >> 5;
    const int l    = lane & (G - 1);
    const int lrow = lane >> 2;                   // local row within warp
    const unsigned mask = 0xffffffffu;

    float* sW = sm + wid * WBUF;
    const int warpRow0 = blockIdx.x * RPC + wid * RWPW;

    // bc arrays + CTA-wide uniformity check (bc == 1 everywhere?)
    int pred = 1;
    if (tid < NN) {
        float bcv = (tid <= NN - 2) ? h0s[tid] * h0p[tid] : 0.0f;
        bcS[tid]  = bcv;
        bthS[tid] = (tid == 0) ? 0.0f : h0s[tid - 1] * h0p[tid - 1];
        pred = (tid <= NN - 2) ? (bcv == 1.0f) : 1;
    }
    int uniformBC = __syncthreads_and(pred);      // also orders bcS/bthS writes

    // ---- warp-local coalesced in-staging: sW[row][j] = he + h0d ----
    {
        const float4* h4 = (const float4*)he;
        const float4* d4 = (const float4*)h0d;
        float4* sW4 = (float4*)sW;
        size_t gmax = (size_t)Brows * SIN4 - 1;
        size_t gbase = (size_t)warpRow0 * SIN4;
        #pragma unroll
        for (int k = 0; k < 5; k++) {
            int idx = lane + 32 * k;              // 0..159
            int c = idx % SIN4;
            size_t gidx = gbase + idx;
            if (gidx > gmax) gidx = gmax;
            float4 hv = __ldg(h4 + gidx);
            float4 dv = __ldg(d4 + c);
            float4 v; v.x = hv.x + dv.x; v.y = hv.y + dv.y;
            v.z = hv.z + dv.z; v.w = hv.w + dv.w;
            sW4[idx] = v;
        }
    }
    __syncwarp();

    if (uniformBC) bk_core<true >(sW, bthS, bcS, l, lrow, mask);
    else           bk_core<false>(sW, bthS, bcS, l, lrow, mask);
    __syncwarp();

    // ---- coalesced out: smem (stride 41 f4) -> global float4 ----
    {
        const float4* so4 = (const float4*)sW;
        float4* out4 = (float4*)out + (size_t)warpRow0 * (NN / 2);
        #pragma unroll
        for (int k = 0; k < 10; k++) {
            int idx = lane + 32 * k;              // 0..319
            int r = idx / (NN / 2);
            int c = idx - r * (NN / 2);
            if (warpRow0 + r < Brows)
                out4[idx] = so4[r * SOUT4 + c];
        }
    }
}

extern "C" void kernel_launch(void* const* d_in, const int* in_sizes, int n_in,
                              void* d_out, int out_size)
{
    const float* he  = (const float*)d_in[0];   // he_diag (B*N)
    const float* h0d = (const float*)d_in[1];   // h0_diag (N)
    const float* h0s = (const float*)d_in[2];   // h0_sub  (N-1)
    const float* h0p = (const float*)d_in[3];   // h0_super(N-1)

    int Brows = in_sizes[0] / NN;
    size_t smem = (size_t)(TPB / 32) * WBUF * sizeof(float);   // 41,984 B

    cudaFuncSetAttribute(bk_green_scan14_kernel,
                         cudaFuncAttributeMaxDynamicSharedMemorySize, (int)smem);

    int grid = (Brows + RPC - 1) / RPC;
    bk_green_scan14_kernel<<<grid, TPB, smem>>>(he, h0d, h0s, h0p, (float*)d_out, Brows);
}

// round 15
// speedup vs baseline: 1.2152x; 1.0655x over previous
#include <cuda_runtime.h>
#include <cstdint>

#define NN    80          // row length N
#define G     4           // threads per row
#define C     20          // recursion steps per thread (G*C == NN)
#define TPB   256
#define RPC   (TPB / G)   // rows per tile = 64
#define TPC   2           // tiles per CTA
#define RWPW  8           // rows per warp per tile
#define SIN4  20          // in view: float4 per row
#define SOUT4 41          // out view: float4 row stride
#define IN1OFF 328        // f4 offset of tile-1 in buffer (out region is [0,328))
#define WB4    488        // per-warp f4 total (7808 B)

static __device__ __forceinline__ uint32_t smem_u32(const void* p) {
    uint32_t a;
    asm("{ .reg .u64 t; cvta.to.shared.u64 t, %1; cvt.u32.u64 %0, t; }"
        : "=r"(a) : "l"(p));
    return a;
}
__device__ __forceinline__ void cp16(uint32_t dst, const void* src) {
    asm volatile("cp.async.cg.shared.global [%0], [%1], 16;" :: "r"(dst), "l"(src));
}
#define CP_COMMIT()  asm volatile("cp.async.commit_group;")
#define CP_WAIT(n)   asm volatile("cp.async.wait_group %0;" :: "n"(n))

// One transfer-matrix step: new_top = (a - i)*x - b*y ; new_bottom = x.
__device__ __forceinline__ void mstep(float a, float b,
                                      float& xr, float& xi, float& yr, float& yi)
{
    float nr = a * xr + xi - b * yr;
    float ni = a * xi - xr - b * yi;
    yr = xr; yi = xi;
    xr = nr; xi = ni;
}

// 2x2 complex matmul C = A*B. Layout: {00r,00i,01r,01i,10r,10i,11r,11i}
__device__ __forceinline__ void mmul(const float* A, const float* B, float* Cm)
{
    Cm[0] = A[0]*B[0] - A[1]*B[1] + A[2]*B[4] - A[3]*B[5];
    Cm[1] = A[0]*B[1] + A[1]*B[0] + A[2]*B[5] + A[3]*B[4];
    Cm[2] = A[0]*B[2] - A[1]*B[3] + A[2]*B[6] - A[3]*B[7];
    Cm[3] = A[0]*B[3] + A[1]*B[2] + A[2]*B[7] + A[3]*B[6];
    Cm[4] = A[4]*B[0] - A[5]*B[1] + A[6]*B[4] - A[7]*B[5];
    Cm[5] = A[4]*B[1] + A[5]*B[0] + A[6]*B[5] + A[7]*B[4];
    Cm[6] = A[4]*B[2] - A[5]*B[3] + A[6]*B[6] - A[7]*B[7];
    Cm[7] = A[4]*B[3] + A[5]*B[2] + A[6]*B[7] + A[7]*B[6];
}

// Full per-tile work: a_reg load (+h0d), scan compute, out staging, global store.
// UB = true -> all bc == 1.0f (verified); b's become literals.
template<bool UB>
__device__ __forceinline__ void run_tile(float* sW, int inoff,
                                         const float4* h0dS4,
                                         const float* bthS, const float* bcS,
                                         float4* out4g, int rowBase,
                                         int l, int lrow, int lane,
                                         int Brows, unsigned mask)
{
    const int j0 = C * l;

    // ---- a-chunk: in-buffer LDS.128 (conflict-free) + broadcast h0d add ----
    float a_reg[C];
    {
        const float4* s4 = (const float4*)sW + inoff + lrow * SIN4 + l * 5;
        #pragma unroll
        for (int q = 0; q < C / 4; q++) {
            float4 v = s4[q];
            float4 dv = h0dS4[l * 5 + q];        // quad-uniform -> broadcast
            a_reg[4*q+0] = v.x + dv.x; a_reg[4*q+1] = v.y + dv.y;
            a_reg[4*q+2] = v.z + dv.z; a_reg[4*q+3] = v.w + dv.w;
        }
    }
    __syncwarp();   // out staging below may overwrite in0 region

    // ---- build THETA chunk matrix (2 columns) ----
    float Jp[8] = {1.f,0.f, 0.f,0.f, 0.f,0.f, 1.f,0.f};
    #pragma unroll
    for (int r = 0; r < C; r++) {
        float at = a_reg[r];
        float bt = UB ? ((r == 0 && l == 0) ? 0.f : 1.f) : bthS[j0 + r];
        mstep(at, bt, Jp[0], Jp[1], Jp[4], Jp[5]);   // col 0
        mstep(at, bt, Jp[2], Jp[3], Jp[6], Jp[7]);   // col 1
    }
    float Js[8];
    #pragma unroll
    for (int i = 0; i < 8; i++) Js[i] = Jp[i];

    // ---- round d=1: full combines, both scans ----
    {
        float Tu[8], Td[8], Ru[8], Rd[8];
        #pragma unroll
        for (int i = 0; i < 8; i++) Tu[i] = __shfl_up_sync(mask, Jp[i], 1, G);
        #pragma unroll
        for (int i = 0; i < 8; i++) Td[i] = __shfl_down_sync(mask, Js[i], 1, G);
        mmul(Jp, Tu, Ru);           // own * received
        mmul(Td, Js, Rd);           // received * own
        bool useu = (l >= 1);
        bool used = (l <= G - 2);
        #pragma unroll
        for (int i = 0; i < 8; i++) {
            Jp[i] = useu ? Ru[i] : Jp[i];
            Js[i] = used ? Rd[i] : Js[i];
        }
    }

    // ---- round d=2 (final): partial combines ----
    {
        float Tu0 = __shfl_up_sync(mask, Jp[0], 2, G);
        float Tu1 = __shfl_up_sync(mask, Jp[1], 2, G);
        float Tu4 = __shfl_up_sync(mask, Jp[4], 2, G);
        float Tu5 = __shfl_up_sync(mask, Jp[5], 2, G);
        float Ru0 = Jp[0]*Tu0 - Jp[1]*Tu1 + Jp[2]*Tu4 - Jp[3]*Tu5;
        float Ru1 = Jp[0]*Tu1 + Jp[1]*Tu0 + Jp[2]*Tu5 + Jp[3]*Tu4;
        float Ru4 = Jp[4]*Tu0 - Jp[5]*Tu1 + Jp[6]*Tu4 - Jp[7]*Tu5;
        float Ru5 = Jp[4]*Tu1 + Jp[5]*Tu0 + Jp[6]*Tu5 + Jp[7]*Tu4;
        bool useu = (l >= 2);
        Jp[0] = useu ? Ru0 : Jp[0];
        Jp[1] = useu ? Ru1 : Jp[1];
        Jp[4] = useu ? Ru4 : Jp[4];
        Jp[5] = useu ? Ru5 : Jp[5];

        float Td0 = __shfl_down_sync(mask, Js[0], 2, G);
        float Td1 = __shfl_down_sync(mask, Js[1], 2, G);
        float Td2 = __shfl_down_sync(mask, Js[2], 2, G);
        float Td3 = __shfl_down_sync(mask, Js[3], 2, G);
        float Rd0 = Td0*Js[0] - Td1*Js[1] + Td2*Js[4] - Td3*Js[5];
        float Rd1 = Td0*Js[1] + Td1*Js[0] + Td2*Js[5] + Td3*Js[4];
        float Rd2 = Td0*Js[2] - Td1*Js[3] + Td2*Js[6] - Td3*Js[7];
        float Rd3 = Td0*Js[3] + Td1*Js[2] + Td2*Js[7] + Td3*Js[6];
        bool used = (l <= G - 3);
        Js[0] = used ? Rd0 : Js[0];
        Js[1] = used ? Rd1 : Js[1];
        Js[2] = used ? Rd2 : Js[2];
        Js[3] = used ? Rd3 : Js[3];
    }

    // denominator: theta_N = [Jp(lane G-1)]_00 ; e = conj(theta_N)/|theta_N|^2
    float exr, exi;
    {
        float dr = __shfl_sync(mask, Jp[0], G - 1, G);
        float di = __shfl_sync(mask, Jp[1], G - 1, G);
        float inv = 1.0f / (dr * dr + di * di);
        exr = dr * inv; exi = -di * inv;
    }

    // theta exclusive prefix state, scaled by e (theta' = e*theta)
    float sxr, sxi, syr, syi;
    {
        float q0 = __shfl_up_sync(mask, Jp[0], 1, G);
        float q1 = __shfl_up_sync(mask, Jp[1], 1, G);
        float q4 = __shfl_up_sync(mask, Jp[4], 1, G);
        float q5 = __shfl_up_sync(mask, Jp[5], 1, G);
        float xr = (l == 0) ? 1.f : q0;
        float xi = (l == 0) ? 0.f : q1;
        float yr = (l == 0) ? 0.f : q4;
        float yi = (l == 0) ? 0.f : q5;
        sxr = xr * exr - xi * exi;  sxi = xr * exi + xi * exr;
        syr = yr * exr - yi * exi;  syi = yr * exi + yi * exr;
    }

    // phi boundary from exclusive suffix T(p), p=j0+C
    float pxr, pxi, qyr, qyi;
    {
        float q0 = __shfl_down_sync(mask, Js[0], 1, G);
        float q1 = __shfl_down_sync(mask, Js[1], 1, G);
        float q2 = __shfl_down_sync(mask, Js[2], 1, G);
        float q3 = __shfl_down_sync(mask, Js[3], 1, G);
        float nbinv = UB ? -1.0f : (-1.0f / bcS[j0 + C - 1]);  // l==G-1 selected away
        pxr = (l == G - 1) ? 1.f : q0;
        pxi = (l == G - 1) ? 0.f : q1;
        qyr = (l == G - 1) ? 0.f : (q2 * nbinv);
        qyi = (l == G - 1) ? 0.f : (q3 * nbinv);
    }

    // ---- phi replay into registers ----
    float phr[C], phi_[C];
    #pragma unroll
    for (int r = 0; r < C; r++) {
        phr[r] = pxr; phi_[r] = pxi;
        float ap = a_reg[C-1-r];
        float bp = UB ? ((r == 0 && l == G - 1) ? 0.f : 1.f)
                      : bcS[j0 + C - 1 - r];
        mstep(ap, bp, pxr, pxi, qyr, qyi);
    }

    // ---- theta' replay fused with g = theta' * phi, staged to smem ----
    {
        float4* so4 = (float4*)sW + lrow * SOUT4 + l * (C / 2);
        float gx = 0.f, gy = 0.f;
        #pragma unroll
        for (int r = 0; r < C; r++) {
            float qr = phr[C-1-r], qi = phi_[C-1-r];
            float g0 = sxr * qr - sxi * qi;
            float g1 = sxr * qi + sxi * qr;
            if ((r & 1) == 0) { gx = g0; gy = g1; }
            else {
                float4 g; g.x = gx; g.y = gy; g.z = g0; g.w = g1;
                so4[r >> 1] = g;
            }
            float at = a_reg[r];
            float bt = UB ? ((r == 0 && l == 0) ? 0.f : 1.f) : bthS[j0 + r];
            mstep(at, bt, sxr, sxi, syr, syi);
        }
    }
    __syncwarp();

    // ---- coalesced out: smem (stride 41 f4) -> global float4 ----
    {
        const float4* so4 = (const float4*)sW;
        float4* og = out4g + (size_t)rowBase * (NN / 2);
        #pragma unroll
        for (int k = 0; k < 10; k++) {
            int idx = lane + 32 * k;              // 0..319
            int r = idx / (NN / 2);
            int c = idx - r * (NN / 2);
            if (rowBase + r < Brows)
                og[idx] = so4[r * SOUT4 + c];
        }
    }
    __syncwarp();   // all lanes done reading out region before next tile's staging
}

__global__ __launch_bounds__(TPB, 3)
void bk_green_scan15_kernel(const float* __restrict__ he,
                            const float* __restrict__ h0d,
                            const float* __restrict__ h0s,
                            const float* __restrict__ h0p,
                            float* __restrict__ out,
                            int Brows)
{
    extern __shared__ float sm[];                 // 8 warps * WB4 float4
    __shared__ float  bthS[NN];                   // theta beta: bc[k-1], bthS[0]=0
    __shared__ float  bcS[NN];                    // bc[m], bcS[NN-1]=0
    __shared__ float4 h0dS4[NN / 4];              // h0_diag as float4

    const int tid  = threadIdx.x;
    const int lane = tid & 31;
    const int wid  = tid >> 5;
    const int l    = lane & (G - 1);
    const int lrow = lane >> 2;
    const unsigned mask = 0xffffffffu;

    float* sW = sm + wid * (WB4 * 4);
    const uint32_t sWu = smem_u32(sW);
    const int ctaRow0 = blockIdx.x * (TPC * RPC);

    // ---- issue cp.async for both tiles immediately (2 commit groups) ----
    {
        const float4* h4 = (const float4*)he;
        size_t gmax = (size_t)Brows * SIN4 - 1;
        #pragma unroll
        for (int t = 0; t < TPC; t++) {
            size_t gbase = (size_t)(ctaRow0 + t * RPC + wid * RWPW) * SIN4;
            uint32_t dbase = sWu + (t == 0 ? 0 : IN1OFF) * 16;
            #pragma unroll
            for (int k = 0; k < 5; k++) {
                int idx = lane + 32 * k;          // 0..159
                size_t gidx = gbase + idx;
                if (gidx > gmax) gidx = gmax;
                cp16(dbase + idx * 16, h4 + gidx);
            }
            CP_COMMIT();
        }
    }

    // ---- bc/h0d arrays + CTA-wide uniformity check (overlaps copy latency) ----
    int pred = 1;
    if (tid < NN) {
        float bcv = (tid <= NN - 2) ? h0s[tid] * h0p[tid] : 0.0f;
        bcS[tid]  = bcv;
        bthS[tid] = (tid == 0) ? 0.0f : h0s[tid - 1] * h0p[tid - 1];
        pred = (tid <= NN - 2) ? (bcv == 1.0f) : 1;
    }
    if (tid < NN / 4) h0dS4[tid] = ((const float4*)h0d)[tid];
    int uniformBC = __syncthreads_and(pred);

    float4* out4g = (float4*)out;

    if (uniformBC) {
        #pragma unroll 1
        for (int t = 0; t < TPC; t++) {
            if (t == 0) { CP_WAIT(1); } else { CP_WAIT(0); }
            __syncwarp();
            run_tile<true >(sW, t == 0 ? 0 : IN1OFF, h0dS4, bthS, bcS,
                            out4g, ctaRow0 + t * RPC + wid * RWPW,
                            l, lrow, lane, Brows, mask);
        }
    } else {
        #pragma unroll 1
        for (int t = 0; t < TPC; t++) {
            if (t == 0) { CP_WAIT(1); } else { CP_WAIT(0); }
            __syncwarp();
            run_tile<false>(sW, t == 0 ? 0 : IN1OFF, h0dS4, bthS, bcS,
                            out4g, ctaRow0 + t * RPC + wid * RWPW,
                            l, lrow, lane, Brows, mask);
        }
    }
}

extern "C" void kernel_launch(void* const* d_in, const int* in_sizes, int n_in,
                              void* d_out, int out_size)
{
    const float* he  = (const float*)d_in[0];   // he_diag (B*N)
    const float* h0d = (const float*)d_in[1];   // h0_diag (N)
    const float* h0s = (const float*)d_in[2];   // h0_sub  (N-1)
    const float* h0p = (const float*)d_in[3];   // h0_super(N-1)

    int Brows = in_sizes[0] / NN;
    size_t smem = (size_t)(TPB / 32) * WB4 * 16;   // 62,464 B

    cudaFuncSetAttribute(bk_green_scan15_kernel,
                         cudaFuncAttributeMaxDynamicSharedMemorySize, (int)smem);

    int grid = (Brows + TPC * RPC - 1) / (TPC * RPC);
    bk_green_scan15_kernel<<<grid, TPB, smem>>>(he, h0d, h0s, h0p, (float*)d_out, Brows);
}

// round 17
// speedup vs baseline: 1.2267x; 1.0094x over previous
#include <cuda_runtime.h>
#include <cstdint>

#define NN    80          // row length N
#define G     4           // threads per row
#define C     20          // recursion steps per thread (G*C == NN)
#define TPB   256
#define RPC   (TPB / G)   // rows per tile = 64
#define TPC   4           // tiles per CTA
#define RWPW  8           // rows per warp per tile
#define SIN4  20          // in view: float4 per row
#define SOUT4 41          // out view: float4 row stride
#define SLOTB 328         // f4 offset of input slot B (slot A = 0)
#define OUTB1 160         // f4 out-region base for odd tiles (even tiles: 0)
#define WB4   488         // per-warp f4 total (7808 B)

static __device__ __forceinline__ uint32_t smem_u32(const void* p) {
    uint32_t a;
    asm("{ .reg .u64 t; cvta.to.shared.u64 t, %1; cvt.u32.u64 %0, t; }"
        : "=r"(a) : "l"(p));
    return a;
}
__device__ __forceinline__ void cp16(uint32_t dst, const void* src) {
    asm volatile("cp.async.cg.shared.global [%0], [%1], 16;" :: "r"(dst), "l"(src));
}
#define CP_COMMIT()  asm volatile("cp.async.commit_group;")

// One transfer-matrix step: new_top = (a - i)*x - b*y ; new_bottom = x.
__device__ __forceinline__ void mstep(float a, float b,
                                      float& xr, float& xi, float& yr, float& yi)
{
    float nr = a * xr + xi - b * yr;
    float ni = a * xi - xr - b * yi;
    yr = xr; yi = xi;
    xr = nr; xi = ni;
}

// 2x2 complex matmul C = A*B. Layout: {00r,00i,01r,01i,10r,10i,11r,11i}
__device__ __forceinline__ void mmul(const float* A, const float* B, float* Cm)
{
    Cm[0] = A[0]*B[0] - A[1]*B[1] + A[2]*B[4] - A[3]*B[5];
    Cm[1] = A[0]*B[1] + A[1]*B[0] + A[2]*B[5] + A[3]*B[4];
    Cm[2] = A[0]*B[2] - A[1]*B[3] + A[2]*B[6] - A[3]*B[7];
    Cm[3] = A[0]*B[3] + A[1]*B[2] + A[2]*B[7] + A[3]*B[6];
    Cm[4] = A[4]*B[0] - A[5]*B[1] + A[6]*B[4] - A[7]*B[5];
    Cm[5] = A[4]*B[1] + A[5]*B[0] + A[6]*B[5] + A[7]*B[4];
    Cm[6] = A[4]*B[2] - A[5]*B[3] + A[6]*B[6] - A[7]*B[7];
    Cm[7] = A[4]*B[3] + A[5]*B[2] + A[6]*B[7] + A[7]*B[6];
}

// Per-tile work. inoff: input slot f4 offset; outoff: out-region f4 base.
// Out region [outoff, outoff+328) overlaps ONLY this tile's input slot.
// UB = true -> all bc == 1.0f (verified); b's become literals.
template<bool UB>
__device__ __forceinline__ void run_tile(float* sW, int inoff, int outoff,
                                         const float4* __restrict__ h0d4,
                                         const float* bthS, const float* bcS,
                                         float4* out4g, int rowBase,
                                         int l, int lrow, int lane,
                                         int Brows, unsigned mask)
{
    const int j0 = C * l;

    // ---- a-chunk: in-slot LDS.128 (conflict-free) + broadcast __ldg h0d ----
    float a_reg[C];
    {
        const float4* s4 = (const float4*)sW + inoff + lrow * SIN4 + l * 5;
        #pragma unroll
        for (int q = 0; q < C / 4; q++) {
            float4 v = s4[q];
            float4 dv = __ldg(h0d4 + l * 5 + q);   // quad-uniform -> L1 broadcast
            a_reg[4*q+0] = v.x + dv.x; a_reg[4*q+1] = v.y + dv.y;
            a_reg[4*q+2] = v.z + dv.z; a_reg[4*q+3] = v.w + dv.w;
        }
    }
    __syncwarp();   // out staging below may overwrite this tile's input slot

    // ---- build THETA chunk matrix (2 columns) ----
    float Jp[8] = {1.f,0.f, 0.f,0.f, 0.f,0.f, 1.f,0.f};
    #pragma unroll
    for (int r = 0; r < C; r++) {
        float at = a_reg[r];
        float bt = UB ? ((r == 0 && l == 0) ? 0.f : 1.f) : bthS[j0 + r];
        mstep(at, bt, Jp[0], Jp[1], Jp[4], Jp[5]);   // col 0
        mstep(at, bt, Jp[2], Jp[3], Jp[6], Jp[7]);   // col 1
    }
    float Js[8];
    #pragma unroll
    for (int i = 0; i < 8; i++) Js[i] = Jp[i];

    // ---- round d=1: full combines, both scans ----
    {
        float Tu[8], Td[8], Ru[8], Rd[8];
        #pragma unroll
        for (int i = 0; i < 8; i++) Tu[i] = __shfl_up_sync(mask, Jp[i], 1, G);
        #pragma unroll
        for (int i = 0; i < 8; i++) Td[i] = __shfl_down_sync(mask, Js[i], 1, G);
        mmul(Jp, Tu, Ru);           // own * received
        mmul(Td, Js, Rd);           // received * own
        bool useu = (l >= 1);
        bool used = (l <= G - 2);
        #pragma unroll
        for (int i = 0; i < 8; i++) {
            Jp[i] = useu ? Ru[i] : Jp[i];
            Js[i] = used ? Rd[i] : Js[i];
        }
    }

    // ---- round d=2 (final): partial combines ----
    {
        float Tu0 = __shfl_up_sync(mask, Jp[0], 2, G);
        float Tu1 = __shfl_up_sync(mask, Jp[1], 2, G);
        float Tu4 = __shfl_up_sync(mask, Jp[4], 2, G);
        float Tu5 = __shfl_up_sync(mask, Jp[5], 2, G);
        float Ru0 = Jp[0]*Tu0 - Jp[1]*Tu1 + Jp[2]*Tu4 - Jp[3]*Tu5;
        float Ru1 = Jp[0]*Tu1 + Jp[1]*Tu0 + Jp[2]*Tu5 + Jp[3]*Tu4;
        float Ru4 = Jp[4]*Tu0 - Jp[5]*Tu1 + Jp[6]*Tu4 - Jp[7]*Tu5;
        float Ru5 = Jp[4]*Tu1 + Jp[5]*Tu0 + Jp[6]*Tu5 + Jp[7]*Tu4;
        bool useu = (l >= 2);
        Jp[0] = useu ? Ru0 : Jp[0];
        Jp[1] = useu ? Ru1 : Jp[1];
        Jp[4] = useu ? Ru4 : Jp[4];
        Jp[5] = useu ? Ru5 : Jp[5];

        float Td0 = __shfl_down_sync(mask, Js[0], 2, G);
        float Td1 = __shfl_down_sync(mask, Js[1], 2, G);
        float Td2 = __shfl_down_sync(mask, Js[2], 2, G);
        float Td3 = __shfl_down_sync(mask, Js[3], 2, G);
        float Rd0 = Td0*Js[0] - Td1*Js[1] + Td2*Js[4] - Td3*Js[5];
        float Rd1 = Td0*Js[1] + Td1*Js[0] + Td2*Js[5] + Td3*Js[4];
        float Rd2 = Td0*Js[2] - Td1*Js[3] + Td2*Js[6] - Td3*Js[7];
        float Rd3 = Td0*Js[3] + Td1*Js[2] + Td2*Js[7] + Td3*Js[6];
        bool used = (l <= G - 3);
        Js[0] = used ? Rd0 : Js[0];
        Js[1] = used ? Rd1 : Js[1];
        Js[2] = used ? Rd2 : Js[2];
        Js[3] = used ? Rd3 : Js[3];
    }

    // denominator: theta_N = [Jp(lane G-1)]_00 ; e = conj(theta_N)/|theta_N|^2
    float exr, exi;
    {
        float dr = __shfl_sync(mask, Jp[0], G - 1, G);
        float di = __shfl_sync(mask, Jp[1], G - 1, G);
        float inv = 1.0f / (dr * dr + di * di);
        exr = dr * inv; exi = -di * inv;
    }

    // theta exclusive prefix state, scaled by e (theta' = e*theta)
    float sxr, sxi, syr, syi;
    {
        float q0 = __shfl_up_sync(mask, Jp[0], 1, G);
        float q1 = __shfl_up_sync(mask, Jp[1], 1, G);
        float q4 = __shfl_up_sync(mask, Jp[4], 1, G);
        float q5 = __shfl_up_sync(mask, Jp[5], 1, G);
        float xr = (l == 0) ? 1.f : q0;
        float xi = (l == 0) ? 0.f : q1;
        float yr = (l == 0) ? 0.f : q4;
        float yi = (l == 0) ? 0.f : q5;
        sxr = xr * exr - xi * exi;  sxi = xr * exi + xi * exr;
        syr = yr * exr - yi * exi;  syi = yr * exi + yi * exr;
    }

    // phi boundary from exclusive suffix T(p), p=j0+C
    float pxr, pxi, qyr, qyi;
    {
        float q0 = __shfl_down_sync(mask, Js[0], 1, G);
        float q1 = __shfl_down_sync(mask, Js[1], 1, G);
        float q2 = __shfl_down_sync(mask, Js[2], 1, G);
        float q3 = __shfl_down_sync(mask, Js[3], 1, G);
        float nbinv = UB ? -1.0f : (-1.0f / bcS[j0 + C - 1]);  // l==G-1 selected away
        pxr = (l == G - 1) ? 1.f : q0;
        pxi = (l == G - 1) ? 0.f : q1;
        qyr = (l == G - 1) ? 0.f : (q2 * nbinv);
        qyi = (l == G - 1) ? 0.f : (q3 * nbinv);
    }

    // ---- phi replay into registers ----
    float phr[C], phi_[C];
    #pragma unroll
    for (int r = 0; r < C; r++) {
        phr[r] = pxr; phi_[r] = pxi;
        float ap = a_reg[C-1-r];
        float bp = UB ? ((r == 0 && l == G - 1) ? 0.f : 1.f)
                      : bcS[j0 + C - 1 - r];
        mstep(ap, bp, pxr, pxi, qyr, qyi);
    }

    // ---- theta' replay fused with g = theta' * phi, staged to smem ----
    {
        float4* so4 = (float4*)sW + outoff + lrow * SOUT4 + l * (C / 2);
        float gx = 0.f, gy = 0.f;
        #pragma unroll
        for (int r = 0; r < C; r++) {
            float qr = phr[C-1-r], qi = phi_[C-1-r];
            float g0 = sxr * qr - sxi * qi;
            float g1 = sxr * qi + sxi * qr;
            if ((r & 1) == 0) { gx = g0; gy = g1; }
            else {
                float4 g; g.x = gx; g.y = gy; g.z = g0; g.w = g1;
                so4[r >> 1] = g;
            }
            float at = a_reg[r];
            float bt = UB ? ((r == 0 && l == 0) ? 0.f : 1.f) : bthS[j0 + r];
            mstep(at, bt, sxr, sxi, syr, syi);
        }
    }
    __syncwarp();

    // ---- coalesced out: smem (stride 41 f4) -> global float4 ----
    {
        const float4* so4 = (const float4*)sW + outoff;
        float4* og = out4g + (size_t)rowBase * (NN / 2);
        #pragma unroll
        for (int k = 0; k < 10; k++) {
            int idx = lane + 32 * k;              // 0..319
            int r = idx / (NN / 2);
            int c = idx - r * (NN / 2);
            if (rowBase + r < Brows)
                og[idx] = so4[r * SOUT4 + c];
        }
    }
    __syncwarp();   // epilogue reads done before next prefetch targets this slot
}

// Issue the 5 cp.async for one warp-tile into slot (f4 offset soff).
__device__ __forceinline__ void prefetch_tile(uint32_t sWu, int soff,
                                              const float4* h4, size_t gbase,
                                              size_t gmax, int lane)
{
    uint32_t dbase = sWu + (uint32_t)soff * 16;
    #pragma unroll
    for (int k = 0; k < 5; k++) {
        int idx = lane + 32 * k;                  // 0..159
        size_t gidx = gbase + idx;
        if (gidx > gmax) gidx = gmax;
        cp16(dbase + idx * 16, h4 + gidx);
    }
}

__global__ __launch_bounds__(TPB, 3)
void bk_green_scan17_kernel(const float* __restrict__ he,
                            const float* __restrict__ h0d,
                            const float* __restrict__ h0s,
                            const float* __restrict__ h0p,
                            float* __restrict__ out,
                            int Brows)
{
    extern __shared__ float sm[];                 // 8 warps * WB4 float4
    __shared__ float bthS[NN];                    // cold path only
    __shared__ float bcS[NN];                     // cold path only

    const int tid  = threadIdx.x;
    const int lane = tid & 31;
    const int wid  = tid >> 5;
    const int l    = lane & (G - 1);
    const int lrow = lane >> 2;
    const unsigned mask = 0xffffffffu;

    float* sW = sm + wid * (WB4 * 4);
    const uint32_t sWu = smem_u32(sW);
    const int ctaRow0 = blockIdx.x * (TPC * RPC);
    const float4* h4 = (const float4*)he;
    const float4* h0d4 = (const float4*)h0d;
    const size_t gmax = (size_t)Brows * SIN4 - 1;

    // ---- prefetch tiles 0 (slot A) and 1 (slot B); one group each ----
    prefetch_tile(sWu, 0, h4,
                  (size_t)(ctaRow0 + 0 * RPC + wid * RWPW) * SIN4, gmax, lane);
    CP_COMMIT();
    prefetch_tile(sWu, SLOTB, h4,
                  (size_t)(ctaRow0 + 1 * RPC + wid * RWPW) * SIN4, gmax, lane);
    CP_COMMIT();

    // cold-path beta arrays (read only if !uniform)
    if (tid < NN) {
        bcS[tid]  = (tid <= NN - 2) ? h0s[tid] * h0p[tid] : 0.0f;
        bthS[tid] = (tid == 0) ? 0.0f : h0s[tid - 1] * h0p[tid - 1];
    }

    // per-warp bc-uniformity check: identical inputs -> CTA-uniform result
    int p = 1;
    #pragma unroll
    for (int i = 0; i < 3; i++) {
        int idx = lane + 32 * i;
        if (idx <= NN - 2) p &= (h0s[idx] * h0p[idx] == 1.0f);
    }
    int uniformBC = __all_sync(mask, p);

    float4* out4g = (float4*)out;

    // Group algebra (commits ONLY on real prefetches; groups G0..G3):
    //   t=0: pending {G0,G1} -> wait 1 (G0 done). run. prefetch t2 -> G2.
    //   t=1: pending {G1,G2} -> wait 1 (G1 done). run. prefetch t3 -> G3.
    //   t=2: pending {G2,G3} -> wait 1 (G2 done). run. no commit.
    //   t=3: pending {G3}    -> wait 0 (G3 done). run.
    if (uniformBC) {
        #pragma unroll 1
        for (int t = 0; t < TPC; t++) {
            if (t == TPC - 1) asm volatile("cp.async.wait_group 0;");
            else              asm volatile("cp.async.wait_group 1;");
            __syncwarp();
            run_tile<true >(sW, (t & 1) * SLOTB, (t & 1) * OUTB1,
                            h0d4, bthS, bcS,
                            out4g, ctaRow0 + t * RPC + wid * RWPW,
                            l, lrow, lane, Brows, mask);
            if (t + 2 < TPC) {
                prefetch_tile(sWu, (t & 1) * SLOTB, h4,
                              (size_t)(ctaRow0 + (t + 2) * RPC + wid * RWPW) * SIN4,
                              gmax, lane);
                CP_COMMIT();
            }
        }
    } else {
        __syncthreads();                          // order bthS/bcS writes
        #pragma unroll 1
        for (int t = 0; t < TPC; t++) {
            if (t == TPC - 1) asm volatile("cp.async.wait_group 0;");
            else              asm volatile("cp.async.wait_group 1;");
            __syncwarp();
            run_tile<false>(sW, (t & 1) * SLOTB, (t & 1) * OUTB1,
                            h0d4, bthS, bcS,
                            out4g, ctaRow0 + t * RPC + wid * RWPW,
                            l, lrow, lane, Brows, mask);
            if (t + 2 < TPC) {
                prefetch_tile(sWu, (t & 1) * SLOTB, h4,
                              (size_t)(ctaRow0 + (t + 2) * RPC + wid * RWPW) * SIN4,
                              gmax, lane);
                CP_COMMIT();
            }
        }
    }
}

extern "C" void kernel_launch(void* const* d_in, const int* in_sizes, int n_in,
                              void* d_out, int out_size)
{
    const float* he  = (const float*)d_in[0];   // he_diag (B*N)
    const float* h0d = (const float*)d_in[1];   // h0_diag (N)
    const float* h0s = (const float*)d_in[2];   // h0_sub  (N-1)
    const float* h0p = (const float*)d_in[3];   // h0_super(N-1)

    int Brows = in_sizes[0] / NN;
    size_t smem = (size_t)(TPB / 32) * WB4 * 16;   // 62,464 B

    cudaFuncSetAttribute(bk_green_scan17_kernel,
                         cudaFuncAttributeMaxDynamicSharedMemorySize, (int)smem);

    int grid = (Brows + TPC * RPC - 1) / (TPC * RPC);
    bk_green_scan17_kernel<<<grid, TPB, smem>>>(he, h0d, h0s, h0p, (float*)d_out, Brows);
}